// round 4
// baseline (speedup 1.0000x reference)
#include <cuda_runtime.h>

#define RNUM 2000
#define DDIM 128
#define HNUM 4
#define CAPZ 512
#define CAPE 64
#define SPLIT 4
#define GREG 8

// ---- scratch (static device globals; no allocation) ----
__device__ float g_q[DDIM];
__device__ float g_a[HNUM * DDIM];
__device__ float g_c[HNUM];
__device__ int   g_count[RNUM];
__device__ int   g_ecount[RNUM];
__device__ int   g_sorted[RNUM * CAPZ];               // row indices bucketed by zone
__device__ int   g_esrc[RNUM * CAPE];                 // edge sources bucketed by dst
__device__ float g_pxbar[RNUM * SPLIT * HNUM * DDIM]; // per-(region,sub) weighted sums
__device__ float g_pden[RNUM * SPLIT * HNUM];         // per-(region,sub) denominators
__device__ float g_hh[RNUM * DDIM];

// ---- prep: block 0 computes q, a = (q^T Wk)/sqrt(D), c; block 1 zeroes counters ----
__global__ void prep_kernel(const float* __restrict__ S, const float* __restrict__ Wq,
                            const float* __restrict__ bq, const float* __restrict__ Wk,
                            const float* __restrict__ bk) {
    if (blockIdx.x == 1) {
        for (int i = threadIdx.x; i < RNUM; i += blockDim.x) {
            g_count[i] = 0;
            g_ecount[i] = 0;
        }
        return;
    }
    __shared__ float sS[DDIM];
    __shared__ float sq[DDIM];
    int i = threadIdx.x;  // 128 threads
    sS[i] = S[i];
    __syncthreads();
    float qi = bq[i];
    for (int j = 0; j < DDIM; j++) qi = fmaf(sS[j], Wq[i * DDIM + j], qi);
    sq[i] = qi;
    g_q[i] = qi;
    __syncthreads();
    const float invs = 0.08838834764831845f;  // 1/sqrt(128)
    for (int h = 0; h < HNUM; h++) {
        float s = 0.f;
        for (int d = 0; d < 32; d++)
            s = fmaf(sq[h * 32 + d], Wk[(h * 32 + d) * DDIM + i], s);
        g_a[h * DDIM + i] = s * invs;
    }
    if (i < HNUM) {
        float s = 0.f;
        for (int d = 0; d < 32; d++) s = fmaf(sq[i * 32 + d], bk[i * 32 + d], s);
        g_c[i] = s * invs;
    }
}

// ---- single-pass bucketed scatter: rows by zone (4/thread via int4), edges by dst ----
__global__ void scatter_kernel(const int* __restrict__ zone, const int* __restrict__ adj,
                               int N, int E) {
    int t = blockIdx.x * blockDim.x + threadIdx.x;
    int nQuads = N >> 2;
    if (t < nQuads) {
        int4 z = __ldg((const int4*)zone + t);
        int b = t * 4;
        int p0 = atomicAdd(&g_count[z.x], 1);
        int p1 = atomicAdd(&g_count[z.y], 1);
        int p2 = atomicAdd(&g_count[z.z], 1);
        int p3 = atomicAdd(&g_count[z.w], 1);
        if (p0 < CAPZ) g_sorted[z.x * CAPZ + p0] = b;
        if (p1 < CAPZ) g_sorted[z.y * CAPZ + p1] = b + 1;
        if (p2 < CAPZ) g_sorted[z.z * CAPZ + p2] = b + 2;
        if (p3 < CAPZ) g_sorted[z.w * CAPZ + p3] = b + 3;
        return;
    }
    int u = t - nQuads;
    int rem = N & 3;
    if (u < rem) {
        int idx = (nQuads << 2) + u;
        int z = zone[idx];
        int p = atomicAdd(&g_count[z], 1);
        if (p < CAPZ) g_sorted[z * CAPZ + p] = idx;
        return;
    }
    u -= rem;
    if (u < E) {
        int src = adj[u];
        int dst = adj[E + u];
        int p = atomicAdd(&g_ecount[dst], 1);
        if (p < CAPE) g_esrc[dst * CAPE + p] = src;
    }
}

// ---- partial: streaming phase. blockIdx = region*SPLIT + sub. Software-pipelined
// gathered reads of x; accumulates exp-weighted sums per (region, sub). No atomics.
__global__ __launch_bounds__(128) void partial_kernel(const float* __restrict__ x) {
    __shared__ float swacc[4][HNUM][DDIM];
    __shared__ float swden[4][HNUM];

    const unsigned F = 0xffffffffu;
    int rb = blockIdx.x;
    int r = rb >> 2, sub = rb & 3;
    int tid = threadIdx.x;
    int w = tid >> 5, lane = tid & 31;
    int lh = lane & 3;

    int cnt = g_count[r];
    if (cnt > CAPZ) cnt = CAPZ;
    int q4 = (cnt + 3) >> 2;
    int begin = sub * q4;
    int end = begin + q4;
    if (end > cnt) end = cnt;
    const int* lst = g_sorted + r * CAPZ;

    float areg[HNUM][4];
#pragma unroll
    for (int h = 0; h < HNUM; h++)
#pragma unroll
        for (int j = 0; j < 4; j++)
            areg[h][j] = g_a[h * DDIM + lane * 4 + j];
    float cper = g_c[lh];

    float acc[4][4];
    float den[4] = {0.f, 0.f, 0.f, 0.f};
#pragma unroll
    for (int k = 0; k < 4; k++)
#pragma unroll
        for (int j = 0; j < 4; j++) acc[k][j] = 0.f;

    int myb = begin + w * 4;
    if (myb < end) {
        // prologue loads
        float4 cur[4];
#pragma unroll
        for (int u = 0; u < 4; u++) {
            int i = myb + u;
            int ii = (i < end) ? i : (end - 1);
            int n = lst[ii];
            cur[u] = __ldg((const float4*)(x + (size_t)n * DDIM) + lane);
        }
        for (int base = myb; base < end; base += 16) {
            int nb = base + 16;
            float4 nxt[4];
            if (nb < end) {
                // issue next group's loads BEFORE computing current group
#pragma unroll
                for (int u = 0; u < 4; u++) {
                    int i = nb + u;
                    int ii = (i < end) ? i : (end - 1);
                    int n = lst[ii];
                    nxt[u] = __ldg((const float4*)(x + (size_t)n * DDIM) + lane);
                }
            }
#pragma unroll
            for (int u = 0; u < 4; u++) {
                bool valid = (base + u) < end;
                float p0 = areg[0][0] * cur[u].x;
                p0 = fmaf(areg[0][1], cur[u].y, p0);
                p0 = fmaf(areg[0][2], cur[u].z, p0);
                p0 = fmaf(areg[0][3], cur[u].w, p0);
                float p1 = areg[1][0] * cur[u].x;
                p1 = fmaf(areg[1][1], cur[u].y, p1);
                p1 = fmaf(areg[1][2], cur[u].z, p1);
                p1 = fmaf(areg[1][3], cur[u].w, p1);
                float p2 = areg[2][0] * cur[u].x;
                p2 = fmaf(areg[2][1], cur[u].y, p2);
                p2 = fmaf(areg[2][2], cur[u].z, p2);
                p2 = fmaf(areg[2][3], cur[u].w, p2);
                float p3 = areg[3][0] * cur[u].x;
                p3 = fmaf(areg[3][1], cur[u].y, p3);
                p3 = fmaf(areg[3][2], cur[u].z, p3);
                p3 = fmaf(areg[3][3], cur[u].w, p3);
                bool b0 = lane & 1;
                bool b1 = lane & 2;
                float rA = (b0 ? p1 : p0) + __shfl_xor_sync(F, b0 ? p0 : p1, 1);
                float rB = (b0 ? p3 : p2) + __shfl_xor_sync(F, b0 ? p2 : p3, 1);
                float rr = (b1 ? rB : rA) + __shfl_xor_sync(F, b1 ? rA : rB, 2);
                rr += __shfl_xor_sync(F, rr, 4);
                rr += __shfl_xor_sync(F, rr, 8);
                rr += __shfl_xor_sync(F, rr, 16);
                float e0 = valid ? __expf(rr + cper) : 0.f;   // head lh
                float e1 = __shfl_xor_sync(F, e0, 1);
                float e2 = __shfl_xor_sync(F, e0, 2);
                float e3 = __shfl_xor_sync(F, e0, 3);
                den[0] += e0; den[1] += e1; den[2] += e2; den[3] += e3;
                acc[0][0] = fmaf(e0, cur[u].x, acc[0][0]);
                acc[0][1] = fmaf(e0, cur[u].y, acc[0][1]);
                acc[0][2] = fmaf(e0, cur[u].z, acc[0][2]);
                acc[0][3] = fmaf(e0, cur[u].w, acc[0][3]);
                acc[1][0] = fmaf(e1, cur[u].x, acc[1][0]);
                acc[1][1] = fmaf(e1, cur[u].y, acc[1][1]);
                acc[1][2] = fmaf(e1, cur[u].z, acc[1][2]);
                acc[1][3] = fmaf(e1, cur[u].w, acc[1][3]);
                acc[2][0] = fmaf(e2, cur[u].x, acc[2][0]);
                acc[2][1] = fmaf(e2, cur[u].y, acc[2][1]);
                acc[2][2] = fmaf(e2, cur[u].z, acc[2][2]);
                acc[2][3] = fmaf(e2, cur[u].w, acc[2][3]);
                acc[3][0] = fmaf(e3, cur[u].x, acc[3][0]);
                acc[3][1] = fmaf(e3, cur[u].y, acc[3][1]);
                acc[3][2] = fmaf(e3, cur[u].z, acc[3][2]);
                acc[3][3] = fmaf(e3, cur[u].w, acc[3][3]);
            }
#pragma unroll
            for (int u = 0; u < 4; u++) cur[u] = nxt[u];
        }
    }
    // stage per-warp partials: acc[k] belongs to head lh^k, dims 4*lane..+3
#pragma unroll
    for (int k = 0; k < 4; k++) {
        int h = lh ^ k;
        swacc[w][h][lane * 4 + 0] = acc[k][0];
        swacc[w][h][lane * 4 + 1] = acc[k][1];
        swacc[w][h][lane * 4 + 2] = acc[k][2];
        swacc[w][h][lane * 4 + 3] = acc[k][3];
    }
    if (lane < 4) {
#pragma unroll
        for (int k = 0; k < 4; k++) swden[w][lh ^ k] = den[k];
    }
    __syncthreads();
    // block-reduce across 4 warps and write partials (coalesced)
    for (int p = tid; p < HNUM * DDIM; p += 128) {
        int h = p >> 7, j = p & 127;
        g_pxbar[(size_t)rb * (HNUM * DDIM) + p] =
            swacc[0][h][j] + swacc[1][h][j] + swacc[2][h][j] + swacc[3][h][j];
    }
    if (tid < HNUM)
        g_pden[rb * HNUM + tid] =
            swden[0][tid] + swden[1][tid] + swden[2][tid] + swden[3][tid];
}

// ---- finalize: reduce SPLIT partials, then Wv -> seed residual -> rFF -> Wg.
// GREG regions per block so weight rows hit L1 after the first region.
__global__ __launch_bounds__(128) void finalize_kernel(
    const float* __restrict__ Wv, const float* __restrict__ bv,
    const float* __restrict__ Wo, const float* __restrict__ bo,
    const float* __restrict__ Wg) {
    __shared__ float sxbar[HNUM][DDIM];
    __shared__ float sden[HNUM];
    __shared__ float sO[DDIM];
    __shared__ float sO2[DDIM];
    int tid = threadIdx.x;
    for (int g = 0; g < GREG; g++) {
        int r = blockIdx.x * GREG + g;
        for (int p = tid; p < HNUM * DDIM; p += 128) {
            size_t b = (size_t)r * SPLIT * (HNUM * DDIM);
            float s = g_pxbar[b + p] + g_pxbar[b + 512 + p] +
                      g_pxbar[b + 1024 + p] + g_pxbar[b + 1536 + p];
            sxbar[p >> 7][p & 127] = s;
        }
        if (tid < HNUM) {
            int b = r * SPLIT * HNUM;
            sden[tid] = g_pden[b + tid] + g_pden[b + 4 + tid] +
                        g_pden[b + 8 + tid] + g_pden[b + 12 + tid];
        }
        __syncthreads();
        // pooled = Wv_row(i) . xbar[h] / den + bv ; O = q + pooled
        {
            int i = tid, h = tid >> 5;
            float dn = sden[h];
            const float4* wr = (const float4*)(Wv + i * DDIM);
            const float4* xb = (const float4*)&sxbar[h][0];
            float s = 0.f;
#pragma unroll 8
            for (int j = 0; j < 32; j++) {
                float4 wv = __ldg(wr + j);
                float4 xx = xb[j];
                s = fmaf(wv.x, xx.x, s);
                s = fmaf(wv.y, xx.y, s);
                s = fmaf(wv.z, xx.z, s);
                s = fmaf(wv.w, xx.w, s);
            }
            float pooled = (dn > 0.f) ? (s / dn + bv[i]) : 0.f;
            sO[i] = g_q[i] + pooled;
        }
        __syncthreads();
        // O2 = O + relu(O @ Wo^T + bo)
        {
            int i = tid;
            const float4* wr = (const float4*)(Wo + i * DDIM);
            const float4* ov = (const float4*)sO;
            float s = bo[i];
#pragma unroll 8
            for (int j = 0; j < 32; j++) {
                float4 wv = __ldg(wr + j);
                float4 xx = ov[j];
                s = fmaf(wv.x, xx.x, s);
                s = fmaf(wv.y, xx.y, s);
                s = fmaf(wv.z, xx.z, s);
                s = fmaf(wv.w, xx.w, s);
            }
            sO2[i] = sO[i] + fmaxf(s, 0.f);
        }
        __syncthreads();
        // hh = O2 @ Wg^T
        {
            int i = tid;
            const float4* wr = (const float4*)(Wg + i * DDIM);
            const float4* ov = (const float4*)sO2;
            float s = 0.f;
#pragma unroll 8
            for (int j = 0; j < 32; j++) {
                float4 wv = __ldg(wr + j);
                float4 xx = ov[j];
                s = fmaf(wv.x, xx.x, s);
                s = fmaf(wv.y, xx.y, s);
                s = fmaf(wv.z, xx.z, s);
                s = fmaf(wv.w, xx.w, s);
            }
            g_hh[r * DDIM + i] = s;
        }
        __syncthreads();  // protect smem before next region overwrites
    }
}

// ---- GCN gather (bucketed by dst) + self loop + bias + PReLU ----
__global__ void gather_kernel(const float* __restrict__ bg,
                              const float* __restrict__ prelu_w,
                              float* __restrict__ out) {
    int r = blockIdx.x, i = threadIdx.x;
    int ec = g_ecount[r];
    int ecl = (ec > CAPE) ? CAPE : ec;
    float degr = (float)(ec + 1);
    float disr = rsqrtf(degr);
    float accv = g_hh[r * DDIM + i] / degr;  // self-loop: dis_r^2
    const int* es = g_esrc + r * CAPE;
    for (int k = 0; k < ecl; k++) {
        int src = es[k];
        float nrm = disr * rsqrtf((float)(g_ecount[src] + 1));
        accv = fmaf(nrm, g_hh[src * DDIM + i], accv);
    }
    float v = accv + bg[i];
    out[r * DDIM + i] = (v > 0.f) ? v : prelu_w[i] * v;
}

extern "C" void kernel_launch(void* const* d_in, const int* in_sizes, int n_in,
                              void* d_out, int out_size) {
    const float* x    = (const float*)d_in[0];
    const int*   zone = (const int*)d_in[1];
    const int*   adj  = (const int*)d_in[2];
    const float* S    = (const float*)d_in[3];
    const float* Wq   = (const float*)d_in[4];
    const float* bq   = (const float*)d_in[5];
    const float* Wk   = (const float*)d_in[6];
    const float* bk   = (const float*)d_in[7];
    const float* Wv   = (const float*)d_in[8];
    const float* bv   = (const float*)d_in[9];
    const float* Wo   = (const float*)d_in[10];
    const float* bo   = (const float*)d_in[11];
    const float* Wg   = (const float*)d_in[12];
    const float* bg   = (const float*)d_in[13];
    const float* pw   = (const float*)d_in[14];
    int N = in_sizes[0] / DDIM;
    int E = in_sizes[2] / 2;

    prep_kernel<<<2, 128>>>(S, Wq, bq, Wk, bk);
    int totalT = (N >> 2) + (N & 3) + E;
    scatter_kernel<<<(totalT + 255) / 256, 256>>>(zone, adj, N, E);
    partial_kernel<<<RNUM * SPLIT, 128>>>(x);
    finalize_kernel<<<RNUM / GREG, 128>>>(Wv, bv, Wo, bo, Wg);
    gather_kernel<<<RNUM, DDIM>>>(bg, pw, (float*)d_out);
}

// round 5
// speedup vs baseline: 1.1658x; 1.1658x over previous
#include <cuda_runtime.h>

#define RNUM 2000
#define DDIM 128
#define HNUM 4
#define CAPZ 512
#define CAPE 64
#define SPLIT 4

// ---- scratch (static device globals; no allocation) ----
__device__ float g_q[DDIM];
__device__ float g_a[HNUM * DDIM];
__device__ float g_c[HNUM];
__device__ int   g_count[RNUM];
__device__ int   g_ecount[RNUM];
__device__ int   g_sorted[RNUM * CAPZ];               // row indices bucketed by zone
__device__ int   g_esrc[RNUM * CAPE];                 // edge sources bucketed by dst
__device__ float g_pxbar[RNUM * SPLIT * HNUM * DDIM]; // per-(region,sub) weighted sums
__device__ float g_pden[RNUM * SPLIT * HNUM];         // per-(region,sub) denominators
__device__ float g_hh[RNUM * DDIM];

// ---- prep: block 0 computes q, a = (q^T Wk)/sqrt(D), c; block 1 zeroes counters ----
__global__ void prep_kernel(const float* __restrict__ S, const float* __restrict__ Wq,
                            const float* __restrict__ bq, const float* __restrict__ Wk,
                            const float* __restrict__ bk) {
    if (blockIdx.x == 1) {
        for (int i = threadIdx.x; i < RNUM; i += blockDim.x) {
            g_count[i] = 0;
            g_ecount[i] = 0;
        }
        return;
    }
    __shared__ float sS[DDIM];
    __shared__ float sq[DDIM];
    int i = threadIdx.x;  // 128 threads
    sS[i] = S[i];
    __syncthreads();
    float qi = bq[i];
    for (int j = 0; j < DDIM; j++) qi = fmaf(sS[j], Wq[i * DDIM + j], qi);
    sq[i] = qi;
    g_q[i] = qi;
    __syncthreads();
    const float invs = 0.08838834764831845f;  // 1/sqrt(128)
    for (int h = 0; h < HNUM; h++) {
        float s = 0.f;
        for (int d = 0; d < 32; d++)
            s = fmaf(sq[h * 32 + d], Wk[(h * 32 + d) * DDIM + i], s);
        g_a[h * DDIM + i] = s * invs;
    }
    if (i < HNUM) {
        float s = 0.f;
        for (int d = 0; d < 32; d++) s = fmaf(sq[i * 32 + d], bk[i * 32 + d], s);
        g_c[i] = s * invs;
    }
}

// ---- single-pass bucketed scatter: rows by zone (4/thread via int4), edges by dst ----
__global__ void scatter_kernel(const int* __restrict__ zone, const int* __restrict__ adj,
                               int N, int E) {
    int t = blockIdx.x * blockDim.x + threadIdx.x;
    int nQuads = N >> 2;
    if (t < nQuads) {
        int4 z = __ldg((const int4*)zone + t);
        int b = t * 4;
        int p0 = atomicAdd(&g_count[z.x], 1);
        int p1 = atomicAdd(&g_count[z.y], 1);
        int p2 = atomicAdd(&g_count[z.z], 1);
        int p3 = atomicAdd(&g_count[z.w], 1);
        if (p0 < CAPZ) g_sorted[z.x * CAPZ + p0] = b;
        if (p1 < CAPZ) g_sorted[z.y * CAPZ + p1] = b + 1;
        if (p2 < CAPZ) g_sorted[z.z * CAPZ + p2] = b + 2;
        if (p3 < CAPZ) g_sorted[z.w * CAPZ + p3] = b + 3;
        return;
    }
    int u = t - nQuads;
    int rem = N & 3;
    if (u < rem) {
        int idx = (nQuads << 2) + u;
        int z = zone[idx];
        int p = atomicAdd(&g_count[z], 1);
        if (p < CAPZ) g_sorted[z * CAPZ + p] = idx;
        return;
    }
    u -= rem;
    if (u < E) {
        int src = adj[u];
        int dst = adj[E + u];
        int p = atomicAdd(&g_ecount[dst], 1);
        if (p < CAPE) g_esrc[dst * CAPE + p] = src;
    }
}

// ---- partial: streaming phase. blockIdx = region*SPLIT + sub. Software-pipelined
// gathered reads of x; accumulates exp-weighted sums per (region, sub). No atomics.
__global__ __launch_bounds__(128) void partial_kernel(const float* __restrict__ x) {
    __shared__ float swacc[4][HNUM][DDIM];
    __shared__ float swden[4][HNUM];

    const unsigned F = 0xffffffffu;
    int rb = blockIdx.x;
    int r = rb >> 2, sub = rb & 3;
    int tid = threadIdx.x;
    int w = tid >> 5, lane = tid & 31;
    int lh = lane & 3;

    int cnt = g_count[r];
    if (cnt > CAPZ) cnt = CAPZ;
    int q4 = (cnt + 3) >> 2;
    int begin = sub * q4;
    int end = begin + q4;
    if (end > cnt) end = cnt;
    const int* lst = g_sorted + r * CAPZ;

    float areg[HNUM][4];
#pragma unroll
    for (int h = 0; h < HNUM; h++)
#pragma unroll
        for (int j = 0; j < 4; j++)
            areg[h][j] = g_a[h * DDIM + lane * 4 + j];
    float cper = g_c[lh];

    float acc[4][4];
    float den[4] = {0.f, 0.f, 0.f, 0.f};
#pragma unroll
    for (int k = 0; k < 4; k++)
#pragma unroll
        for (int j = 0; j < 4; j++) acc[k][j] = 0.f;

    int myb = begin + w * 4;
    if (myb < end) {
        // prologue loads
        float4 cur[4];
#pragma unroll
        for (int u = 0; u < 4; u++) {
            int i = myb + u;
            int ii = (i < end) ? i : (end - 1);
            int n = lst[ii];
            cur[u] = __ldg((const float4*)(x + (size_t)n * DDIM) + lane);
        }
        for (int base = myb; base < end; base += 16) {
            int nb = base + 16;
            float4 nxt[4];
            if (nb < end) {
                // issue next group's loads BEFORE computing current group
#pragma unroll
                for (int u = 0; u < 4; u++) {
                    int i = nb + u;
                    int ii = (i < end) ? i : (end - 1);
                    int n = lst[ii];
                    nxt[u] = __ldg((const float4*)(x + (size_t)n * DDIM) + lane);
                }
            }
#pragma unroll
            for (int u = 0; u < 4; u++) {
                bool valid = (base + u) < end;
                float p0 = areg[0][0] * cur[u].x;
                p0 = fmaf(areg[0][1], cur[u].y, p0);
                p0 = fmaf(areg[0][2], cur[u].z, p0);
                p0 = fmaf(areg[0][3], cur[u].w, p0);
                float p1 = areg[1][0] * cur[u].x;
                p1 = fmaf(areg[1][1], cur[u].y, p1);
                p1 = fmaf(areg[1][2], cur[u].z, p1);
                p1 = fmaf(areg[1][3], cur[u].w, p1);
                float p2 = areg[2][0] * cur[u].x;
                p2 = fmaf(areg[2][1], cur[u].y, p2);
                p2 = fmaf(areg[2][2], cur[u].z, p2);
                p2 = fmaf(areg[2][3], cur[u].w, p2);
                float p3 = areg[3][0] * cur[u].x;
                p3 = fmaf(areg[3][1], cur[u].y, p3);
                p3 = fmaf(areg[3][2], cur[u].z, p3);
                p3 = fmaf(areg[3][3], cur[u].w, p3);
                bool b0 = lane & 1;
                bool b1 = lane & 2;
                float rA = (b0 ? p1 : p0) + __shfl_xor_sync(F, b0 ? p0 : p1, 1);
                float rB = (b0 ? p3 : p2) + __shfl_xor_sync(F, b0 ? p2 : p3, 1);
                float rr = (b1 ? rB : rA) + __shfl_xor_sync(F, b1 ? rA : rB, 2);
                rr += __shfl_xor_sync(F, rr, 4);
                rr += __shfl_xor_sync(F, rr, 8);
                rr += __shfl_xor_sync(F, rr, 16);
                float e0 = valid ? __expf(rr + cper) : 0.f;   // head lh
                float e1 = __shfl_xor_sync(F, e0, 1);
                float e2 = __shfl_xor_sync(F, e0, 2);
                float e3 = __shfl_xor_sync(F, e0, 3);
                den[0] += e0; den[1] += e1; den[2] += e2; den[3] += e3;
                acc[0][0] = fmaf(e0, cur[u].x, acc[0][0]);
                acc[0][1] = fmaf(e0, cur[u].y, acc[0][1]);
                acc[0][2] = fmaf(e0, cur[u].z, acc[0][2]);
                acc[0][3] = fmaf(e0, cur[u].w, acc[0][3]);
                acc[1][0] = fmaf(e1, cur[u].x, acc[1][0]);
                acc[1][1] = fmaf(e1, cur[u].y, acc[1][1]);
                acc[1][2] = fmaf(e1, cur[u].z, acc[1][2]);
                acc[1][3] = fmaf(e1, cur[u].w, acc[1][3]);
                acc[2][0] = fmaf(e2, cur[u].x, acc[2][0]);
                acc[2][1] = fmaf(e2, cur[u].y, acc[2][1]);
                acc[2][2] = fmaf(e2, cur[u].z, acc[2][2]);
                acc[2][3] = fmaf(e2, cur[u].w, acc[2][3]);
                acc[3][0] = fmaf(e3, cur[u].x, acc[3][0]);
                acc[3][1] = fmaf(e3, cur[u].y, acc[3][1]);
                acc[3][2] = fmaf(e3, cur[u].z, acc[3][2]);
                acc[3][3] = fmaf(e3, cur[u].w, acc[3][3]);
            }
#pragma unroll
            for (int u = 0; u < 4; u++) cur[u] = nxt[u];
        }
    }
    // stage per-warp partials: acc[k] belongs to head lh^k, dims 4*lane..+3
#pragma unroll
    for (int k = 0; k < 4; k++) {
        int h = lh ^ k;
        swacc[w][h][lane * 4 + 0] = acc[k][0];
        swacc[w][h][lane * 4 + 1] = acc[k][1];
        swacc[w][h][lane * 4 + 2] = acc[k][2];
        swacc[w][h][lane * 4 + 3] = acc[k][3];
    }
    if (lane < 4) {
#pragma unroll
        for (int k = 0; k < 4; k++) swden[w][lh ^ k] = den[k];
    }
    __syncthreads();
    // block-reduce across 4 warps and write partials (coalesced)
    for (int p = tid; p < HNUM * DDIM; p += 128) {
        int h = p >> 7, j = p & 127;
        g_pxbar[(size_t)rb * (HNUM * DDIM) + p] =
            swacc[0][h][j] + swacc[1][h][j] + swacc[2][h][j] + swacc[3][h][j];
    }
    if (tid < HNUM)
        g_pden[rb * HNUM + tid] =
            swden[0][tid] + swden[1][tid] + swden[2][tid] + swden[3][tid];
}

// ---- finalize: one region per block (2000 blocks). Reduce SPLIT partials,
// then Wv -> seed residual -> rFF -> Wg. Dot products use 4 independent
// accumulator chains; weights stay hot in L1 across CTAs on the same SM.
__global__ __launch_bounds__(128) void finalize_kernel(
    const float* __restrict__ Wv, const float* __restrict__ bv,
    const float* __restrict__ Wo, const float* __restrict__ bo,
    const float* __restrict__ Wg) {
    __shared__ float sxbar[HNUM][DDIM];
    __shared__ float sden[HNUM];
    __shared__ float sO[DDIM];
    __shared__ float sO2[DDIM];
    int r = blockIdx.x;
    int tid = threadIdx.x;

    // reduce SPLIT partials into smem
    for (int p = tid; p < HNUM * DDIM; p += 128) {
        size_t b = (size_t)r * SPLIT * (HNUM * DDIM);
        float s = g_pxbar[b + p] + g_pxbar[b + 512 + p] +
                  g_pxbar[b + 1024 + p] + g_pxbar[b + 1536 + p];
        sxbar[p >> 7][p & 127] = s;
    }
    if (tid < HNUM) {
        int b = r * SPLIT * HNUM;
        sden[tid] = g_pden[b + tid] + g_pden[b + 4 + tid] +
                    g_pden[b + 8 + tid] + g_pden[b + 12 + tid];
    }
    __syncthreads();
    // pooled = Wv_row(i) . xbar[h] / den + bv ; O = q + pooled
    {
        int i = tid, h = tid >> 5;
        float dn = sden[h];
        const float4* wr = (const float4*)(Wv + i * DDIM);
        const float4* xb = (const float4*)&sxbar[h][0];
        float s0 = 0.f, s1 = 0.f, s2 = 0.f, s3 = 0.f;
#pragma unroll
        for (int j = 0; j < 32; j += 4) {
            float4 w0 = __ldg(wr + j), w1 = __ldg(wr + j + 1);
            float4 w2 = __ldg(wr + j + 2), w3 = __ldg(wr + j + 3);
            float4 x0 = xb[j], x1 = xb[j + 1], x2 = xb[j + 2], x3 = xb[j + 3];
            s0 = fmaf(w0.x, x0.x, s0); s0 = fmaf(w0.y, x0.y, s0);
            s0 = fmaf(w0.z, x0.z, s0); s0 = fmaf(w0.w, x0.w, s0);
            s1 = fmaf(w1.x, x1.x, s1); s1 = fmaf(w1.y, x1.y, s1);
            s1 = fmaf(w1.z, x1.z, s1); s1 = fmaf(w1.w, x1.w, s1);
            s2 = fmaf(w2.x, x2.x, s2); s2 = fmaf(w2.y, x2.y, s2);
            s2 = fmaf(w2.z, x2.z, s2); s2 = fmaf(w2.w, x2.w, s2);
            s3 = fmaf(w3.x, x3.x, s3); s3 = fmaf(w3.y, x3.y, s3);
            s3 = fmaf(w3.z, x3.z, s3); s3 = fmaf(w3.w, x3.w, s3);
        }
        float s = (s0 + s1) + (s2 + s3);
        float pooled = (dn > 0.f) ? (s / dn + bv[i]) : 0.f;
        sO[i] = g_q[i] + pooled;
    }
    __syncthreads();
    // O2 = O + relu(O @ Wo^T + bo)
    {
        int i = tid;
        const float4* wr = (const float4*)(Wo + i * DDIM);
        const float4* ov = (const float4*)sO;
        float s0 = bo[i], s1 = 0.f, s2 = 0.f, s3 = 0.f;
#pragma unroll
        for (int j = 0; j < 32; j += 4) {
            float4 w0 = __ldg(wr + j), w1 = __ldg(wr + j + 1);
            float4 w2 = __ldg(wr + j + 2), w3 = __ldg(wr + j + 3);
            float4 x0 = ov[j], x1 = ov[j + 1], x2 = ov[j + 2], x3 = ov[j + 3];
            s0 = fmaf(w0.x, x0.x, s0); s0 = fmaf(w0.y, x0.y, s0);
            s0 = fmaf(w0.z, x0.z, s0); s0 = fmaf(w0.w, x0.w, s0);
            s1 = fmaf(w1.x, x1.x, s1); s1 = fmaf(w1.y, x1.y, s1);
            s1 = fmaf(w1.z, x1.z, s1); s1 = fmaf(w1.w, x1.w, s1);
            s2 = fmaf(w2.x, x2.x, s2); s2 = fmaf(w2.y, x2.y, s2);
            s2 = fmaf(w2.z, x2.z, s2); s2 = fmaf(w2.w, x2.w, s2);
            s3 = fmaf(w3.x, x3.x, s3); s3 = fmaf(w3.y, x3.y, s3);
            s3 = fmaf(w3.z, x3.z, s3); s3 = fmaf(w3.w, x3.w, s3);
        }
        float s = (s0 + s1) + (s2 + s3);
        sO2[i] = sO[i] + fmaxf(s, 0.f);
    }
    __syncthreads();
    // hh = O2 @ Wg^T
    {
        int i = tid;
        const float4* wr = (const float4*)(Wg + i * DDIM);
        const float4* ov = (const float4*)sO2;
        float s0 = 0.f, s1 = 0.f, s2 = 0.f, s3 = 0.f;
#pragma unroll
        for (int j = 0; j < 32; j += 4) {
            float4 w0 = __ldg(wr + j), w1 = __ldg(wr + j + 1);
            float4 w2 = __ldg(wr + j + 2), w3 = __ldg(wr + j + 3);
            float4 x0 = ov[j], x1 = ov[j + 1], x2 = ov[j + 2], x3 = ov[j + 3];
            s0 = fmaf(w0.x, x0.x, s0); s0 = fmaf(w0.y, x0.y, s0);
            s0 = fmaf(w0.z, x0.z, s0); s0 = fmaf(w0.w, x0.w, s0);
            s1 = fmaf(w1.x, x1.x, s1); s1 = fmaf(w1.y, x1.y, s1);
            s1 = fmaf(w1.z, x1.z, s1); s1 = fmaf(w1.w, x1.w, s1);
            s2 = fmaf(w2.x, x2.x, s2); s2 = fmaf(w2.y, x2.y, s2);
            s2 = fmaf(w2.z, x2.z, s2); s2 = fmaf(w2.w, x2.w, s2);
            s3 = fmaf(w3.x, x3.x, s3); s3 = fmaf(w3.y, x3.y, s3);
            s3 = fmaf(w3.z, x3.z, s3); s3 = fmaf(w3.w, x3.w, s3);
        }
        g_hh[r * DDIM + i] = (s0 + s1) + (s2 + s3);
    }
}

// ---- GCN gather (bucketed by dst) + self loop + bias + PReLU ----
__global__ void gather_kernel(const float* __restrict__ bg,
                              const float* __restrict__ prelu_w,
                              float* __restrict__ out) {
    int r = blockIdx.x, i = threadIdx.x;
    int ec = g_ecount[r];
    int ecl = (ec > CAPE) ? CAPE : ec;
    float degr = (float)(ec + 1);
    float disr = rsqrtf(degr);
    float accv = g_hh[r * DDIM + i] / degr;  // self-loop: dis_r^2
    const int* es = g_esrc + r * CAPE;
    for (int k = 0; k < ecl; k++) {
        int src = es[k];
        float nrm = disr * rsqrtf((float)(g_ecount[src] + 1));
        accv = fmaf(nrm, g_hh[src * DDIM + i], accv);
    }
    float v = accv + bg[i];
    out[r * DDIM + i] = (v > 0.f) ? v : prelu_w[i] * v;
}

extern "C" void kernel_launch(void* const* d_in, const int* in_sizes, int n_in,
                              void* d_out, int out_size) {
    const float* x    = (const float*)d_in[0];
    const int*   zone = (const int*)d_in[1];
    const int*   adj  = (const int*)d_in[2];
    const float* S    = (const float*)d_in[3];
    const float* Wq   = (const float*)d_in[4];
    const float* bq   = (const float*)d_in[5];
    const float* Wk   = (const float*)d_in[6];
    const float* bk   = (const float*)d_in[7];
    const float* Wv   = (const float*)d_in[8];
    const float* bv   = (const float*)d_in[9];
    const float* Wo   = (const float*)d_in[10];
    const float* bo   = (const float*)d_in[11];
    const float* Wg   = (const float*)d_in[12];
    const float* bg   = (const float*)d_in[13];
    const float* pw   = (const float*)d_in[14];
    int N = in_sizes[0] / DDIM;
    int E = in_sizes[2] / 2;

    prep_kernel<<<2, 128>>>(S, Wq, bq, Wk, bk);
    int totalT = (N >> 2) + (N & 3) + E;
    scatter_kernel<<<(totalT + 255) / 256, 256>>>(zone, adj, N, E);
    partial_kernel<<<RNUM * SPLIT, 128>>>(x);
    finalize_kernel<<<RNUM, 128>>>(Wv, bv, Wo, bo, Wg);
    gather_kernel<<<RNUM, DDIM>>>(bg, pw, (float*)d_out);
}

// round 7
// speedup vs baseline: 1.5882x; 1.3623x over previous
#include <cuda_runtime.h>

#define RNUM 2000
#define DDIM 128
#define HNUM 4
#define CAPZ 512
#define CAPE 64
#define SPLIT 4

// ---- scratch (static device globals; no allocation) ----
__device__ float g_q[DDIM];
__device__ float g_a[HNUM * DDIM];
__device__ float g_c[HNUM];
__device__ int   g_count[RNUM];
__device__ int   g_ecount[RNUM];
__device__ int   g_sorted[RNUM * CAPZ];               // row indices bucketed by zone
__device__ int   g_esrc[RNUM * CAPE];                 // edge sources bucketed by dst
__device__ float g_pxbar[RNUM * SPLIT * HNUM * DDIM]; // per-(region,sub) weighted sums
__device__ float g_pden[RNUM * SPLIT * HNUM];         // per-(region,sub) denominators
__device__ float g_hh[RNUM * DDIM];

// ---- prep: block 0 computes q, a = (q^T Wk)/sqrt(D), c; block 1 zeroes counters ----
__global__ void prep_kernel(const float* __restrict__ S, const float* __restrict__ Wq,
                            const float* __restrict__ bq, const float* __restrict__ Wk,
                            const float* __restrict__ bk) {
    if (blockIdx.x == 1) {
        for (int i = threadIdx.x; i < RNUM; i += blockDim.x) {
            g_count[i] = 0;
            g_ecount[i] = 0;
        }
        return;
    }
    __shared__ float sS[DDIM];
    __shared__ float sq[DDIM];
    int i = threadIdx.x;  // 128 threads
    sS[i] = S[i];
    __syncthreads();
    float qi = bq[i];
    for (int j = 0; j < DDIM; j++) qi = fmaf(sS[j], Wq[i * DDIM + j], qi);
    sq[i] = qi;
    g_q[i] = qi;
    __syncthreads();
    const float invs = 0.08838834764831845f;  // 1/sqrt(128)
    for (int h = 0; h < HNUM; h++) {
        float s = 0.f;
        for (int d = 0; d < 32; d++)
            s = fmaf(sq[h * 32 + d], Wk[(h * 32 + d) * DDIM + i], s);
        g_a[h * DDIM + i] = s * invs;
    }
    if (i < HNUM) {
        float s = 0.f;
        for (int d = 0; d < 32; d++) s = fmaf(sq[i * 32 + d], bk[i * 32 + d], s);
        g_c[i] = s * invs;
    }
}

// ---- single-pass bucketed scatter: rows by zone (4/thread via int4), edges by dst ----
__global__ void scatter_kernel(const int* __restrict__ zone, const int* __restrict__ adj,
                               int N, int E) {
    int t = blockIdx.x * blockDim.x + threadIdx.x;
    int nQuads = N >> 2;
    if (t < nQuads) {
        int4 z = __ldg((const int4*)zone + t);
        int b = t * 4;
        int p0 = atomicAdd(&g_count[z.x], 1);
        int p1 = atomicAdd(&g_count[z.y], 1);
        int p2 = atomicAdd(&g_count[z.z], 1);
        int p3 = atomicAdd(&g_count[z.w], 1);
        if (p0 < CAPZ) g_sorted[z.x * CAPZ + p0] = b;
        if (p1 < CAPZ) g_sorted[z.y * CAPZ + p1] = b + 1;
        if (p2 < CAPZ) g_sorted[z.z * CAPZ + p2] = b + 2;
        if (p3 < CAPZ) g_sorted[z.w * CAPZ + p3] = b + 3;
        return;
    }
    int u = t - nQuads;
    int rem = N & 3;
    if (u < rem) {
        int idx = (nQuads << 2) + u;
        int z = zone[idx];
        int p = atomicAdd(&g_count[z], 1);
        if (p < CAPZ) g_sorted[z * CAPZ + p] = idx;
        return;
    }
    u -= rem;
    if (u < E) {
        int src = adj[u];
        int dst = adj[E + u];
        int p = atomicAdd(&g_ecount[dst], 1);
        if (p < CAPE) g_esrc[dst * CAPE + p] = src;
    }
}

// ---- partial: streaming phase. blockIdx = region*SPLIT + sub. Software-pipelined
// gathered reads of x; accumulates exp-weighted sums per (region, sub). No atomics.
__global__ __launch_bounds__(128) void partial_kernel(const float* __restrict__ x) {
    __shared__ float swacc[4][HNUM][DDIM];
    __shared__ float swden[4][HNUM];

    const unsigned F = 0xffffffffu;
    int rb = blockIdx.x;
    int r = rb >> 2, sub = rb & 3;
    int tid = threadIdx.x;
    int w = tid >> 5, lane = tid & 31;
    int lh = lane & 3;

    int cnt = g_count[r];
    if (cnt > CAPZ) cnt = CAPZ;
    int q4 = (cnt + 3) >> 2;
    int begin = sub * q4;
    int end = begin + q4;
    if (end > cnt) end = cnt;
    const int* lst = g_sorted + r * CAPZ;

    float areg[HNUM][4];
#pragma unroll
    for (int h = 0; h < HNUM; h++)
#pragma unroll
        for (int j = 0; j < 4; j++)
            areg[h][j] = g_a[h * DDIM + lane * 4 + j];
    float cper = g_c[lh];

    float acc[4][4];
    float den[4] = {0.f, 0.f, 0.f, 0.f};
#pragma unroll
    for (int k = 0; k < 4; k++)
#pragma unroll
        for (int j = 0; j < 4; j++) acc[k][j] = 0.f;

    int myb = begin + w * 4;
    if (myb < end) {
        // prologue loads
        float4 cur[4];
#pragma unroll
        for (int u = 0; u < 4; u++) {
            int i = myb + u;
            int ii = (i < end) ? i : (end - 1);
            int n = lst[ii];
            cur[u] = __ldg((const float4*)(x + (size_t)n * DDIM) + lane);
        }
        for (int base = myb; base < end; base += 16) {
            int nb = base + 16;
            float4 nxt[4];
            if (nb < end) {
                // issue next group's loads BEFORE computing current group
#pragma unroll
                for (int u = 0; u < 4; u++) {
                    int i = nb + u;
                    int ii = (i < end) ? i : (end - 1);
                    int n = lst[ii];
                    nxt[u] = __ldg((const float4*)(x + (size_t)n * DDIM) + lane);
                }
            }
#pragma unroll
            for (int u = 0; u < 4; u++) {
                bool valid = (base + u) < end;
                float p0 = areg[0][0] * cur[u].x;
                p0 = fmaf(areg[0][1], cur[u].y, p0);
                p0 = fmaf(areg[0][2], cur[u].z, p0);
                p0 = fmaf(areg[0][3], cur[u].w, p0);
                float p1 = areg[1][0] * cur[u].x;
                p1 = fmaf(areg[1][1], cur[u].y, p1);
                p1 = fmaf(areg[1][2], cur[u].z, p1);
                p1 = fmaf(areg[1][3], cur[u].w, p1);
                float p2 = areg[2][0] * cur[u].x;
                p2 = fmaf(areg[2][1], cur[u].y, p2);
                p2 = fmaf(areg[2][2], cur[u].z, p2);
                p2 = fmaf(areg[2][3], cur[u].w, p2);
                float p3 = areg[3][0] * cur[u].x;
                p3 = fmaf(areg[3][1], cur[u].y, p3);
                p3 = fmaf(areg[3][2], cur[u].z, p3);
                p3 = fmaf(areg[3][3], cur[u].w, p3);
                bool b0 = lane & 1;
                bool b1 = lane & 2;
                float rA = (b0 ? p1 : p0) + __shfl_xor_sync(F, b0 ? p0 : p1, 1);
                float rB = (b0 ? p3 : p2) + __shfl_xor_sync(F, b0 ? p2 : p3, 1);
                float rr = (b1 ? rB : rA) + __shfl_xor_sync(F, b1 ? rA : rB, 2);
                rr += __shfl_xor_sync(F, rr, 4);
                rr += __shfl_xor_sync(F, rr, 8);
                rr += __shfl_xor_sync(F, rr, 16);
                float e0 = valid ? __expf(rr + cper) : 0.f;   // head lh
                float e1 = __shfl_xor_sync(F, e0, 1);
                float e2 = __shfl_xor_sync(F, e0, 2);
                float e3 = __shfl_xor_sync(F, e0, 3);
                den[0] += e0; den[1] += e1; den[2] += e2; den[3] += e3;
                acc[0][0] = fmaf(e0, cur[u].x, acc[0][0]);
                acc[0][1] = fmaf(e0, cur[u].y, acc[0][1]);
                acc[0][2] = fmaf(e0, cur[u].z, acc[0][2]);
                acc[0][3] = fmaf(e0, cur[u].w, acc[0][3]);
                acc[1][0] = fmaf(e1, cur[u].x, acc[1][0]);
                acc[1][1] = fmaf(e1, cur[u].y, acc[1][1]);
                acc[1][2] = fmaf(e1, cur[u].z, acc[1][2]);
                acc[1][3] = fmaf(e1, cur[u].w, acc[1][3]);
                acc[2][0] = fmaf(e2, cur[u].x, acc[2][0]);
                acc[2][1] = fmaf(e2, cur[u].y, acc[2][1]);
                acc[2][2] = fmaf(e2, cur[u].z, acc[2][2]);
                acc[2][3] = fmaf(e2, cur[u].w, acc[2][3]);
                acc[3][0] = fmaf(e3, cur[u].x, acc[3][0]);
                acc[3][1] = fmaf(e3, cur[u].y, acc[3][1]);
                acc[3][2] = fmaf(e3, cur[u].z, acc[3][2]);
                acc[3][3] = fmaf(e3, cur[u].w, acc[3][3]);
            }
#pragma unroll
            for (int u = 0; u < 4; u++) cur[u] = nxt[u];
        }
    }
    // stage per-warp partials: acc[k] belongs to head lh^k, dims 4*lane..+3
#pragma unroll
    for (int k = 0; k < 4; k++) {
        int h = lh ^ k;
        swacc[w][h][lane * 4 + 0] = acc[k][0];
        swacc[w][h][lane * 4 + 1] = acc[k][1];
        swacc[w][h][lane * 4 + 2] = acc[k][2];
        swacc[w][h][lane * 4 + 3] = acc[k][3];
    }
    if (lane < 4) {
#pragma unroll
        for (int k = 0; k < 4; k++) swden[w][lh ^ k] = den[k];
    }
    __syncthreads();
    // block-reduce across 4 warps and write partials (coalesced)
    for (int p = tid; p < HNUM * DDIM; p += 128) {
        int h = p >> 7, j = p & 127;
        g_pxbar[(size_t)rb * (HNUM * DDIM) + p] =
            swacc[0][h][j] + swacc[1][h][j] + swacc[2][h][j] + swacc[3][h][j];
    }
    if (tid < HNUM)
        g_pden[rb * HNUM + tid] =
            swden[0][tid] + swden[1][tid] + swden[2][tid] + swden[3][tid];
}

// ---- finalize: one region per block (2000 blocks). Warp-per-row coalesced GEMV:
// warp w handles rows [32w, 32w+32); lanes read consecutive 16B of each weight row
// (4 L1 wavefronts per warp-LDG instead of 32). Two rows reduced per 5 shuffles.
__global__ __launch_bounds__(128) void finalize_kernel(
    const float* __restrict__ Wv, const float* __restrict__ bv,
    const float* __restrict__ Wo, const float* __restrict__ bo,
    const float* __restrict__ Wg) {
    __shared__ float sxbar[HNUM][DDIM];
    __shared__ float sden[HNUM];
    __shared__ float sO[DDIM];
    __shared__ float sO2[DDIM];
    const unsigned F = 0xffffffffu;
    int r = blockIdx.x;
    int tid = threadIdx.x;
    int w = tid >> 5, lane = tid & 31;
    bool hi = lane & 16;
    bool isw = (lane & 15) == 0;  // writer lanes: 0 and 16

    // reduce SPLIT partials into smem
    for (int p = tid; p < HNUM * DDIM; p += 128) {
        size_t b = (size_t)r * SPLIT * (HNUM * DDIM);
        float s = g_pxbar[b + p] + g_pxbar[b + 512 + p] +
                  g_pxbar[b + 1024 + p] + g_pxbar[b + 1536 + p];
        sxbar[p >> 7][p & 127] = s;
    }
    if (tid < HNUM) {
        int b = r * SPLIT * HNUM;
        sden[tid] = g_pden[b + tid] + g_pden[b + 4 + tid] +
                    g_pden[b + 8 + tid] + g_pden[b + 12 + tid];
    }
    __syncthreads();

    // ---- stage 1: O = q + (Wv . xbar[head]) / den + bv ; warp w == head w
    {
        float dn = sden[w];
        float inv = (dn > 0.f) ? (1.f / dn) : 0.f;
        float4 xv = ((const float4*)&sxbar[w][0])[lane];  // x once per stage
        const float4* Wb = (const float4*)(Wv + (w * 32) * DDIM);
#pragma unroll
        for (int rr = 0; rr < 32; rr += 2) {
            float4 w0 = __ldg(Wb + rr * 32 + lane);
            float4 w1 = __ldg(Wb + (rr + 1) * 32 + lane);
            float d0 = w0.x * xv.x;
            d0 = fmaf(w0.y, xv.y, d0); d0 = fmaf(w0.z, xv.z, d0); d0 = fmaf(w0.w, xv.w, d0);
            float d1 = w1.x * xv.x;
            d1 = fmaf(w1.y, xv.y, d1); d1 = fmaf(w1.z, xv.z, d1); d1 = fmaf(w1.w, xv.w, d1);
            float v = (hi ? d1 : d0) + __shfl_xor_sync(F, hi ? d0 : d1, 16);
            v += __shfl_xor_sync(F, v, 8);
            v += __shfl_xor_sync(F, v, 4);
            v += __shfl_xor_sync(F, v, 2);
            v += __shfl_xor_sync(F, v, 1);
            if (isw) {
                int row = w * 32 + rr + (hi ? 1 : 0);
                float pooled = (dn > 0.f) ? (v * inv + bv[row]) : 0.f;
                sO[row] = g_q[row] + pooled;
            }
        }
    }
    __syncthreads();
    // ---- stage 2: O2 = O + relu(Wo . O + bo)
    {
        float4 xv = ((const float4*)sO)[lane];
        const float4* Wb = (const float4*)(Wo + (w * 32) * DDIM);
#pragma unroll
        for (int rr = 0; rr < 32; rr += 2) {
            float4 w0 = __ldg(Wb + rr * 32 + lane);
            float4 w1 = __ldg(Wb + (rr + 1) * 32 + lane);
            float d0 = w0.x * xv.x;
            d0 = fmaf(w0.y, xv.y, d0); d0 = fmaf(w0.z, xv.z, d0); d0 = fmaf(w0.w, xv.w, d0);
            float d1 = w1.x * xv.x;
            d1 = fmaf(w1.y, xv.y, d1); d1 = fmaf(w1.z, xv.z, d1); d1 = fmaf(w1.w, xv.w, d1);
            float v = (hi ? d1 : d0) + __shfl_xor_sync(F, hi ? d0 : d1, 16);
            v += __shfl_xor_sync(F, v, 8);
            v += __shfl_xor_sync(F, v, 4);
            v += __shfl_xor_sync(F, v, 2);
            v += __shfl_xor_sync(F, v, 1);
            if (isw) {
                int row = w * 32 + rr + (hi ? 1 : 0);
                sO2[row] = sO[row] + fmaxf(v + bo[row], 0.f);
            }
        }
    }
    __syncthreads();
    // ---- stage 3: hh = Wg . O2
    {
        float4 xv = ((const float4*)sO2)[lane];
        const float4* Wb = (const float4*)(Wg + (w * 32) * DDIM);
#pragma unroll
        for (int rr = 0; rr < 32; rr += 2) {
            float4 w0 = __ldg(Wb + rr * 32 + lane);
            float4 w1 = __ldg(Wb + (rr + 1) * 32 + lane);
            float d0 = w0.x * xv.x;
            d0 = fmaf(w0.y, xv.y, d0); d0 = fmaf(w0.z, xv.z, d0); d0 = fmaf(w0.w, xv.w, d0);
            float d1 = w1.x * xv.x;
            d1 = fmaf(w1.y, xv.y, d1); d1 = fmaf(w1.z, xv.z, d1); d1 = fmaf(w1.w, xv.w, d1);
            float v = (hi ? d1 : d0) + __shfl_xor_sync(F, hi ? d0 : d1, 16);
            v += __shfl_xor_sync(F, v, 8);
            v += __shfl_xor_sync(F, v, 4);
            v += __shfl_xor_sync(F, v, 2);
            v += __shfl_xor_sync(F, v, 1);
            if (isw) {
                int row = w * 32 + rr + (hi ? 1 : 0);
                g_hh[r * DDIM + row] = v;
            }
        }
    }
}

// ---- GCN gather (bucketed by dst) + self loop + bias + PReLU ----
__global__ void gather_kernel(const float* __restrict__ bg,
                              const float* __restrict__ prelu_w,
                              float* __restrict__ out) {
    int r = blockIdx.x, i = threadIdx.x;
    int ec = g_ecount[r];
    int ecl = (ec > CAPE) ? CAPE : ec;
    float degr = (float)(ec + 1);
    float disr = rsqrtf(degr);
    float accv = g_hh[r * DDIM + i] / degr;  // self-loop: dis_r^2
    const int* es = g_esrc + r * CAPE;
    for (int k = 0; k < ecl; k++) {
        int src = es[k];
        float nrm = disr * rsqrtf((float)(g_ecount[src] + 1));
        accv = fmaf(nrm, g_hh[src * DDIM + i], accv);
    }
    float v = accv + bg[i];
    out[r * DDIM + i] = (v > 0.f) ? v : prelu_w[i] * v;
}

extern "C" void kernel_launch(void* const* d_in, const int* in_sizes, int n_in,
                              void* d_out, int out_size) {
    const float* x    = (const float*)d_in[0];
    const int*   zone = (const int*)d_in[1];
    const int*   adj  = (const int*)d_in[2];
    const float* S    = (const float*)d_in[3];
    const float* Wq   = (const float*)d_in[4];
    const float* bq   = (const float*)d_in[5];
    const float* Wk   = (const float*)d_in[6];
    const float* bk   = (const float*)d_in[7];
    const float* Wv   = (const float*)d_in[8];
    const float* bv   = (const float*)d_in[9];
    const float* Wo   = (const float*)d_in[10];
    const float* bo   = (const float*)d_in[11];
    const float* Wg   = (const float*)d_in[12];
    const float* bg   = (const float*)d_in[13];
    const float* pw   = (const float*)d_in[14];
    int N = in_sizes[0] / DDIM;
    int E = in_sizes[2] / 2;

    prep_kernel<<<2, 128>>>(S, Wq, bq, Wk, bk);
    int totalT = (N >> 2) + (N & 3) + E;
    scatter_kernel<<<(totalT + 255) / 256, 256>>>(zone, adj, N, E);
    partial_kernel<<<RNUM * SPLIT, 128>>>(x);
    finalize_kernel<<<RNUM, 128>>>(Wv, bv, Wo, bo, Wg);
    gather_kernel<<<RNUM, DDIM>>>(bg, pw, (float*)d_out);
}

// round 9
// speedup vs baseline: 1.6577x; 1.0438x over previous
#include <cuda_runtime.h>

#define RNUM 2000
#define DDIM 128
#define HNUM 4
#define CAPZ 512
#define CAPE 64
#define SPLIT 4

// ---- scratch (static device globals; no allocation) ----
__device__ float g_q[DDIM];
__device__ float g_a[HNUM * DDIM];
__device__ float g_c[HNUM];
__device__ int   g_count[RNUM];
__device__ int   g_ecount[RNUM];
__device__ int   g_sorted[RNUM * CAPZ];               // row indices bucketed by zone
__device__ int   g_esrc[RNUM * CAPE];                 // edge sources bucketed by dst
__device__ float g_pxbar[RNUM * SPLIT * HNUM * DDIM]; // per-(region,sub) weighted sums
__device__ float g_pden[RNUM * SPLIT * HNUM];         // per-(region,sub) denominators
__device__ float g_hh[RNUM * DDIM];

// ---- prep: block 0 computes q, a = (q^T Wk)/sqrt(D), c; block 1 zeroes counters ----
__global__ void prep_kernel(const float* __restrict__ S, const float* __restrict__ Wq,
                            const float* __restrict__ bq, const float* __restrict__ Wk,
                            const float* __restrict__ bk) {
    if (blockIdx.x == 1) {
        for (int i = threadIdx.x; i < RNUM; i += blockDim.x) {
            g_count[i] = 0;
            g_ecount[i] = 0;
        }
        return;
    }
    __shared__ float sS[DDIM];
    __shared__ float sq[DDIM];
    int i = threadIdx.x;  // 128 threads
    sS[i] = S[i];
    __syncthreads();
    float qi = bq[i];
    for (int j = 0; j < DDIM; j++) qi = fmaf(sS[j], Wq[i * DDIM + j], qi);
    sq[i] = qi;
    g_q[i] = qi;
    __syncthreads();
    const float invs = 0.08838834764831845f;  // 1/sqrt(128)
    for (int h = 0; h < HNUM; h++) {
        float s = 0.f;
        for (int d = 0; d < 32; d++)
            s = fmaf(sq[h * 32 + d], Wk[(h * 32 + d) * DDIM + i], s);
        g_a[h * DDIM + i] = s * invs;
    }
    if (i < HNUM) {
        float s = 0.f;
        for (int d = 0; d < 32; d++) s = fmaf(sq[i * 32 + d], bk[i * 32 + d], s);
        g_c[i] = s * invs;
    }
}

// ---- single-pass bucketed scatter: rows by zone (4/thread via int4), edges by dst ----
__global__ void scatter_kernel(const int* __restrict__ zone, const int* __restrict__ adj,
                               int N, int E) {
    int t = blockIdx.x * blockDim.x + threadIdx.x;
    int nQuads = N >> 2;
    if (t < nQuads) {
        int4 z = __ldg((const int4*)zone + t);
        int b = t * 4;
        int p0 = atomicAdd(&g_count[z.x], 1);
        int p1 = atomicAdd(&g_count[z.y], 1);
        int p2 = atomicAdd(&g_count[z.z], 1);
        int p3 = atomicAdd(&g_count[z.w], 1);
        if (p0 < CAPZ) g_sorted[z.x * CAPZ + p0] = b;
        if (p1 < CAPZ) g_sorted[z.y * CAPZ + p1] = b + 1;
        if (p2 < CAPZ) g_sorted[z.z * CAPZ + p2] = b + 2;
        if (p3 < CAPZ) g_sorted[z.w * CAPZ + p3] = b + 3;
        return;
    }
    int u = t - nQuads;
    int rem = N & 3;
    if (u < rem) {
        int idx = (nQuads << 2) + u;
        int z = zone[idx];
        int p = atomicAdd(&g_count[z], 1);
        if (p < CAPZ) g_sorted[z * CAPZ + p] = idx;
        return;
    }
    u -= rem;
    if (u < E) {
        int src = adj[u];
        int dst = adj[E + u];
        int p = atomicAdd(&g_ecount[dst], 1);
        if (p < CAPE) g_esrc[dst * CAPE + p] = src;
    }
}

// ---- partial: streaming phase. blockIdx = region*SPLIT + sub. Software-pipelined
// gathered reads of x; accumulates exp-weighted sums per (region, sub). No atomics.
__global__ __launch_bounds__(128) void partial_kernel(const float* __restrict__ x) {
    __shared__ float swacc[4][HNUM][DDIM];
    __shared__ float swden[4][HNUM];

    const unsigned F = 0xffffffffu;
    int rb = blockIdx.x;
    int r = rb >> 2, sub = rb & 3;
    int tid = threadIdx.x;
    int w = tid >> 5, lane = tid & 31;
    int lh = lane & 3;

    int cnt = g_count[r];
    if (cnt > CAPZ) cnt = CAPZ;
    int q4 = (((cnt + 3) >> 2) + 3) & ~3;  // rows per sub, rounded to multiple of 4
    int begin = sub * q4;
    if (begin > cnt) begin = cnt;
    int end = begin + q4;
    if (end > cnt) end = cnt;
    const int* lst = g_sorted + r * CAPZ;

    float areg[HNUM][4];
#pragma unroll
    for (int h = 0; h < HNUM; h++)
#pragma unroll
        for (int j = 0; j < 4; j++)
            areg[h][j] = g_a[h * DDIM + lane * 4 + j];
    float cper = g_c[lh];

    float acc[4][4];
    float den[4] = {0.f, 0.f, 0.f, 0.f};
#pragma unroll
    for (int k = 0; k < 4; k++)
#pragma unroll
        for (int j = 0; j < 4; j++) acc[k][j] = 0.f;

    // one row's full update; `valid` is warp-uniform (compile-folds on fast path)
    auto dorow = [&](const float4& xv, bool valid) {
        float p0 = areg[0][0] * xv.x;
        p0 = fmaf(areg[0][1], xv.y, p0);
        p0 = fmaf(areg[0][2], xv.z, p0);
        p0 = fmaf(areg[0][3], xv.w, p0);
        float p1 = areg[1][0] * xv.x;
        p1 = fmaf(areg[1][1], xv.y, p1);
        p1 = fmaf(areg[1][2], xv.z, p1);
        p1 = fmaf(areg[1][3], xv.w, p1);
        float p2 = areg[2][0] * xv.x;
        p2 = fmaf(areg[2][1], xv.y, p2);
        p2 = fmaf(areg[2][2], xv.z, p2);
        p2 = fmaf(areg[2][3], xv.w, p2);
        float p3 = areg[3][0] * xv.x;
        p3 = fmaf(areg[3][1], xv.y, p3);
        p3 = fmaf(areg[3][2], xv.z, p3);
        p3 = fmaf(areg[3][3], xv.w, p3);
        bool b0 = lane & 1;
        bool b1 = lane & 2;
        float rA = (b0 ? p1 : p0) + __shfl_xor_sync(F, b0 ? p0 : p1, 1);
        float rB = (b0 ? p3 : p2) + __shfl_xor_sync(F, b0 ? p2 : p3, 1);
        float rr = (b1 ? rB : rA) + __shfl_xor_sync(F, b1 ? rA : rB, 2);
        rr += __shfl_xor_sync(F, rr, 4);
        rr += __shfl_xor_sync(F, rr, 8);
        rr += __shfl_xor_sync(F, rr, 16);
        float e0 = valid ? __expf(rr + cper) : 0.f;   // head lh
        float e1 = __shfl_xor_sync(F, e0, 1);
        float e2 = __shfl_xor_sync(F, e0, 2);
        float e3 = __shfl_xor_sync(F, e0, 3);
        den[0] += e0; den[1] += e1; den[2] += e2; den[3] += e3;
        acc[0][0] = fmaf(e0, xv.x, acc[0][0]);
        acc[0][1] = fmaf(e0, xv.y, acc[0][1]);
        acc[0][2] = fmaf(e0, xv.z, acc[0][2]);
        acc[0][3] = fmaf(e0, xv.w, acc[0][3]);
        acc[1][0] = fmaf(e1, xv.x, acc[1][0]);
        acc[1][1] = fmaf(e1, xv.y, acc[1][1]);
        acc[1][2] = fmaf(e1, xv.z, acc[1][2]);
        acc[1][3] = fmaf(e1, xv.w, acc[1][3]);
        acc[2][0] = fmaf(e2, xv.x, acc[2][0]);
        acc[2][1] = fmaf(e2, xv.y, acc[2][1]);
        acc[2][2] = fmaf(e2, xv.z, acc[2][2]);
        acc[2][3] = fmaf(e2, xv.w, acc[2][3]);
        acc[3][0] = fmaf(e3, xv.x, acc[3][0]);
        acc[3][1] = fmaf(e3, xv.y, acc[3][1]);
        acc[3][2] = fmaf(e3, xv.z, acc[3][2]);
        acc[3][3] = fmaf(e3, xv.w, acc[3][3]);
    };

    // group loader: int4 index load on the (common) fully-valid path
    auto loadgrp = [&](int b, float4* v) {
        if (b + 4 <= end) {
            int4 idx = *(const int4*)(lst + b);  // b is a multiple of 4
            v[0] = __ldcs((const float4*)(x + (size_t)idx.x * DDIM) + lane);
            v[1] = __ldcs((const float4*)(x + (size_t)idx.y * DDIM) + lane);
            v[2] = __ldcs((const float4*)(x + (size_t)idx.z * DDIM) + lane);
            v[3] = __ldcs((const float4*)(x + (size_t)idx.w * DDIM) + lane);
        } else {
            int last = end - 1;
#pragma unroll
            for (int u = 0; u < 4; u++) {
                int i = b + u;
                if (i > last) i = last;
                int n = lst[i];
                v[u] = __ldcs((const float4*)(x + (size_t)n * DDIM) + lane);
            }
        }
    };

    int myb = begin + w * 4;
    if (myb < end) {
        float4 cur[4];
        loadgrp(myb, cur);
        int base = myb;
        for (;;) {
            int nb = base + 16;
            bool more = nb < end;
            float4 nxt[4];
            if (more) loadgrp(nb, nxt);  // next group's loads before current compute
            if (base + 4 <= end) {
                dorow(cur[0], true);
                dorow(cur[1], true);
                dorow(cur[2], true);
                dorow(cur[3], true);
            } else {
                dorow(cur[0], base + 0 < end);
                dorow(cur[1], base + 1 < end);
                dorow(cur[2], base + 2 < end);
                dorow(cur[3], base + 3 < end);
            }
            if (!more) break;
            base = nb;
#pragma unroll
            for (int u = 0; u < 4; u++) cur[u] = nxt[u];
        }
    }
    // stage per-warp partials: acc[k] belongs to head lh^k, dims 4*lane..+3
#pragma unroll
    for (int k = 0; k < 4; k++) {
        int h = lh ^ k;
        swacc[w][h][lane * 4 + 0] = acc[k][0];
        swacc[w][h][lane * 4 + 1] = acc[k][1];
        swacc[w][h][lane * 4 + 2] = acc[k][2];
        swacc[w][h][lane * 4 + 3] = acc[k][3];
    }
    if (lane < 4) {
#pragma unroll
        for (int k = 0; k < 4; k++) swden[w][lh ^ k] = den[k];
    }
    __syncthreads();
    // block-reduce across 4 warps and write partials (coalesced)
    for (int p = tid; p < HNUM * DDIM; p += 128) {
        int h = p >> 7, j = p & 127;
        g_pxbar[(size_t)rb * (HNUM * DDIM) + p] =
            swacc[0][h][j] + swacc[1][h][j] + swacc[2][h][j] + swacc[3][h][j];
    }
    if (tid < HNUM)
        g_pden[rb * HNUM + tid] =
            swden[0][tid] + swden[1][tid] + swden[2][tid] + swden[3][tid];
}

// ---- 8-row coalesced GEMV with 9-shuffle joint fold.
// Wb: base of an 8-row block (row-major, 32 float4 per row). Returns the full
// 32-lane dot for row (b4 + 2*b3 + 4*b2), replicated across lane bits {1,0}.
__device__ __forceinline__ float gemv8_fold(const float4* __restrict__ Wb,
                                            float4 xv, int lane) {
    const unsigned F = 0xffffffffu;
    float d[8];
#pragma unroll
    for (int k = 0; k < 8; k++) {
        float4 wv = __ldg(Wb + k * 32 + lane);
        float t = wv.x * xv.x;
        t = fmaf(wv.y, xv.y, t);
        t = fmaf(wv.z, xv.z, t);
        t = fmaf(wv.w, xv.w, t);
        d[k] = t;
    }
    bool b4 = lane & 16, b3 = lane & 8, b2 = lane & 4;
    float v0 = (b4 ? d[1] : d[0]) + __shfl_xor_sync(F, b4 ? d[0] : d[1], 16);
    float v1 = (b4 ? d[3] : d[2]) + __shfl_xor_sync(F, b4 ? d[2] : d[3], 16);
    float v2 = (b4 ? d[5] : d[4]) + __shfl_xor_sync(F, b4 ? d[4] : d[5], 16);
    float v3 = (b4 ? d[7] : d[6]) + __shfl_xor_sync(F, b4 ? d[6] : d[7], 16);
    float u0 = (b3 ? v1 : v0) + __shfl_xor_sync(F, b3 ? v0 : v1, 8);
    float u1 = (b3 ? v3 : v2) + __shfl_xor_sync(F, b3 ? v2 : v3, 8);
    float s  = (b2 ? u1 : u0) + __shfl_xor_sync(F, b2 ? u0 : u1, 4);
    s += __shfl_xor_sync(F, s, 2);
    s += __shfl_xor_sync(F, s, 1);
    return s;
}

// ---- finalize: one region per block (2000 blocks). Warp w owns rows [32w,32w+32).
// Each stage: 4 iterations of the 8-row fold (8 loads in flight, 9 shuffles).
__global__ __launch_bounds__(128) void finalize_kernel(
    const float* __restrict__ Wv, const float* __restrict__ bv,
    const float* __restrict__ Wo, const float* __restrict__ bo,
    const float* __restrict__ Wg) {
    __shared__ float sxbar[HNUM][DDIM];
    __shared__ float sden[HNUM];
    __shared__ float sO[DDIM];
    __shared__ float sO2[DDIM];
    int r = blockIdx.x;
    int tid = threadIdx.x;
    int w = tid >> 5, lane = tid & 31;
    int rowsel = ((lane >> 4) & 1) | (((lane >> 3) & 1) << 1) | (((lane >> 2) & 1) << 2);
    bool isw = (lane & 3) == 0;

    // reduce SPLIT partials into smem
    for (int p = tid; p < HNUM * DDIM; p += 128) {
        size_t b = (size_t)r * SPLIT * (HNUM * DDIM);
        float s = g_pxbar[b + p] + g_pxbar[b + 512 + p] +
                  g_pxbar[b + 1024 + p] + g_pxbar[b + 1536 + p];
        sxbar[p >> 7][p & 127] = s;
    }
    if (tid < HNUM) {
        int b = r * SPLIT * HNUM;
        sden[tid] = g_pden[b + tid] + g_pden[b + 4 + tid] +
                    g_pden[b + 8 + tid] + g_pden[b + 12 + tid];
    }
    __syncthreads();

    // ---- stage 1: O = q + (Wv . xbar[head]) / den + bv ; warp w == head w
    {
        float dn = sden[w];
        float inv = (dn > 0.f) ? (1.f / dn) : 0.f;
        float4 xv = ((const float4*)&sxbar[w][0])[lane];
        const float4* Wb = (const float4*)(Wv + (w * 32) * DDIM);
#pragma unroll
        for (int t = 0; t < 4; t++) {
            float s = gemv8_fold(Wb + t * 8 * 32, xv, lane);
            if (isw) {
                int row = w * 32 + t * 8 + rowsel;
                float pooled = (dn > 0.f) ? (s * inv + bv[row]) : 0.f;
                sO[row] = g_q[row] + pooled;
            }
        }
    }
    __syncthreads();
    // ---- stage 2: O2 = O + relu(Wo . O + bo)
    {
        float4 xv = ((const float4*)sO)[lane];
        const float4* Wb = (const float4*)(Wo + (w * 32) * DDIM);
#pragma unroll
        for (int t = 0; t < 4; t++) {
            float s = gemv8_fold(Wb + t * 8 * 32, xv, lane);
            if (isw) {
                int row = w * 32 + t * 8 + rowsel;
                sO2[row] = sO[row] + fmaxf(s + bo[row], 0.f);
            }
        }
    }
    __syncthreads();
    // ---- stage 3: hh = Wg . O2
    {
        float4 xv = ((const float4*)sO2)[lane];
        const float4* Wb = (const float4*)(Wg + (w * 32) * DDIM);
#pragma unroll
        for (int t = 0; t < 4; t++) {
            float s = gemv8_fold(Wb + t * 8 * 32, xv, lane);
            if (isw) {
                int row = w * 32 + t * 8 + rowsel;
                g_hh[r * DDIM + row] = s;
            }
        }
    }
}

// ---- GCN gather (bucketed by dst) + self loop + bias + PReLU ----
__global__ void gather_kernel(const float* __restrict__ bg,
                              const float* __restrict__ prelu_w,
                              float* __restrict__ out) {
    int r = blockIdx.x, i = threadIdx.x;
    int ec = g_ecount[r];
    int ecl = (ec > CAPE) ? CAPE : ec;
    float degr = (float)(ec + 1);
    float disr = rsqrtf(degr);
    float accv = g_hh[r * DDIM + i] / degr;  // self-loop: dis_r^2
    const int* es = g_esrc + r * CAPE;
    for (int k = 0; k < ecl; k++) {
        int src = es[k];
        float nrm = disr * rsqrtf((float)(g_ecount[src] + 1));
        accv = fmaf(nrm, g_hh[src * DDIM + i], accv);
    }
    float v = accv + bg[i];
    out[r * DDIM + i] = (v > 0.f) ? v : prelu_w[i] * v;
}

extern "C" void kernel_launch(void* const* d_in, const int* in_sizes, int n_in,
                              void* d_out, int out_size) {
    const float* x    = (const float*)d_in[0];
    const int*   zone = (const int*)d_in[1];
    const int*   adj  = (const int*)d_in[2];
    const float* S    = (const float*)d_in[3];
    const float* Wq   = (const float*)d_in[4];
    const float* bq   = (const float*)d_in[5];
    const float* Wk   = (const float*)d_in[6];
    const float* bk   = (const float*)d_in[7];
    const float* Wv   = (const float*)d_in[8];
    const float* bv   = (const float*)d_in[9];
    const float* Wo   = (const float*)d_in[10];
    const float* bo   = (const float*)d_in[11];
    const float* Wg   = (const float*)d_in[12];
    const float* bg   = (const float*)d_in[13];
    const float* pw   = (const float*)d_in[14];
    int N = in_sizes[0] / DDIM;
    int E = in_sizes[2] / 2;

    prep_kernel<<<2, 128>>>(S, Wq, bq, Wk, bk);
    int totalT = (N >> 2) + (N & 3) + E;
    scatter_kernel<<<(totalT + 255) / 256, 256>>>(zone, adj, N, E);
    partial_kernel<<<RNUM * SPLIT, 128>>>(x);
    finalize_kernel<<<RNUM, 128>>>(Wv, bv, Wo, bo, Wg);
    gather_kernel<<<RNUM, DDIM>>>(bg, pw, (float*)d_out);
}

// round 10
// speedup vs baseline: 1.7520x; 1.0569x over previous
#include <cuda_runtime.h>

#define RNUM 2000
#define DDIM 128
#define HNUM 4
#define CAPZ 512
#define CAPE 64
#define SPLIT 4

// ---- scratch (static device globals; no allocation) ----
__device__ float g_q[DDIM];
__device__ float g_a[HNUM * DDIM];
__device__ float g_c[HNUM];
__device__ int   g_count[RNUM];
__device__ int   g_ecount[RNUM];
__device__ int   g_done[RNUM];
__device__ int   g_sorted[RNUM * CAPZ];               // row indices bucketed by zone
__device__ int   g_esrc[RNUM * CAPE];                 // edge sources bucketed by dst
__device__ float g_pxbar[RNUM * SPLIT * HNUM * DDIM]; // per-(region,sub) weighted sums
__device__ float g_pden[RNUM * SPLIT * HNUM];         // per-(region,sub) denominators
__device__ float g_hh[RNUM * DDIM];

// ---- prep: block 0 computes q, a = (q^T Wk)*log2e/sqrt(D), c; block 1 zeroes ----
__global__ void prep_kernel(const float* __restrict__ S, const float* __restrict__ Wq,
                            const float* __restrict__ bq, const float* __restrict__ Wk,
                            const float* __restrict__ bk) {
    if (blockIdx.x == 1) {
        for (int i = threadIdx.x; i < RNUM; i += blockDim.x) {
            g_count[i] = 0;
            g_ecount[i] = 0;
            g_done[i] = 0;
        }
        return;
    }
    __shared__ float sS[DDIM];
    __shared__ float sq[DDIM];
    int i = threadIdx.x;  // 128 threads
    sS[i] = S[i];
    __syncthreads();
    float qi = bq[i];
    for (int j = 0; j < DDIM; j++) qi = fmaf(sS[j], Wq[i * DDIM + j], qi);
    sq[i] = qi;
    g_q[i] = qi;
    __syncthreads();
    // fold 1/sqrt(128) AND log2(e) into the score coefficients -> bare exp2 later
    const float invs = 0.08838834764831845f * 1.4426950408889634f;
    for (int h = 0; h < HNUM; h++) {
        float s = 0.f;
        for (int d = 0; d < 32; d++)
            s = fmaf(sq[h * 32 + d], Wk[(h * 32 + d) * DDIM + i], s);
        g_a[h * DDIM + i] = s * invs;
    }
    if (i < HNUM) {
        float s = 0.f;
        for (int d = 0; d < 32; d++) s = fmaf(sq[i * 32 + d], bk[i * 32 + d], s);
        g_c[i] = s * invs;
    }
}

// ---- single-pass bucketed scatter: rows by zone (4/thread via int4), edges by dst ----
__global__ void scatter_kernel(const int* __restrict__ zone, const int* __restrict__ adj,
                               int N, int E) {
    int t = blockIdx.x * blockDim.x + threadIdx.x;
    int nQuads = N >> 2;
    if (t < nQuads) {
        int4 z = __ldg((const int4*)zone + t);
        int b = t * 4;
        int p0 = atomicAdd(&g_count[z.x], 1);
        int p1 = atomicAdd(&g_count[z.y], 1);
        int p2 = atomicAdd(&g_count[z.z], 1);
        int p3 = atomicAdd(&g_count[z.w], 1);
        if (p0 < CAPZ) g_sorted[z.x * CAPZ + p0] = b;
        if (p1 < CAPZ) g_sorted[z.y * CAPZ + p1] = b + 1;
        if (p2 < CAPZ) g_sorted[z.z * CAPZ + p2] = b + 2;
        if (p3 < CAPZ) g_sorted[z.w * CAPZ + p3] = b + 3;
        return;
    }
    int u = t - nQuads;
    int rem = N & 3;
    if (u < rem) {
        int idx = (nQuads << 2) + u;
        int z = zone[idx];
        int p = atomicAdd(&g_count[z], 1);
        if (p < CAPZ) g_sorted[z * CAPZ + p] = idx;
        return;
    }
    u -= rem;
    if (u < E) {
        int src = adj[u];
        int dst = adj[E + u];
        int p = atomicAdd(&g_ecount[dst], 1);
        if (p < CAPE) g_esrc[dst * CAPE + p] = src;
    }
}

// ---- 8-row coalesced GEMV with 9-shuffle joint fold.
__device__ __forceinline__ float gemv8_fold(const float4* __restrict__ Wb,
                                            float4 xv, int lane) {
    const unsigned F = 0xffffffffu;
    float d[8];
#pragma unroll
    for (int k = 0; k < 8; k++) {
        float4 wv = __ldg(Wb + k * 32 + lane);
        float t = wv.x * xv.x;
        t = fmaf(wv.y, xv.y, t);
        t = fmaf(wv.z, xv.z, t);
        t = fmaf(wv.w, xv.w, t);
        d[k] = t;
    }
    bool b4 = lane & 16, b3 = lane & 8, b2 = lane & 4;
    float v0 = (b4 ? d[1] : d[0]) + __shfl_xor_sync(F, b4 ? d[0] : d[1], 16);
    float v1 = (b4 ? d[3] : d[2]) + __shfl_xor_sync(F, b4 ? d[2] : d[3], 16);
    float v2 = (b4 ? d[5] : d[4]) + __shfl_xor_sync(F, b4 ? d[4] : d[5], 16);
    float v3 = (b4 ? d[7] : d[6]) + __shfl_xor_sync(F, b4 ? d[6] : d[7], 16);
    float u0 = (b3 ? v1 : v0) + __shfl_xor_sync(F, b3 ? v0 : v1, 8);
    float u1 = (b3 ? v3 : v2) + __shfl_xor_sync(F, b3 ? v2 : v3, 8);
    float s  = (b2 ? u1 : u0) + __shfl_xor_sync(F, b2 ? u0 : u1, 4);
    s += __shfl_xor_sync(F, s, 2);
    s += __shfl_xor_sync(F, s, 1);
    return s;
}

// ---- partial + fused finalize. blockIdx = region*SPLIT + sub.
// Streaming phase accumulates exp-weighted sums; the LAST finishing sub-block
// of each region re-reads the (L2-hot) partials and runs the 3 GEMVs inline.
__global__ __launch_bounds__(128) void partial_kernel(
    const float* __restrict__ x,
    const float* __restrict__ Wv, const float* __restrict__ bv,
    const float* __restrict__ Wo, const float* __restrict__ bo,
    const float* __restrict__ Wg) {
    __shared__ float swacc[4][HNUM][DDIM];   // 8 KB
    __shared__ float swden[4][HNUM];
    __shared__ float sxbar[HNUM][DDIM];      // 2 KB (finalize phase)
    __shared__ float sden[HNUM];
    __shared__ float sO[DDIM];
    __shared__ float sO2[DDIM];
    __shared__ int s_last;

    const unsigned F = 0xffffffffu;
    int rb = blockIdx.x;
    int r = rb >> 2, sub = rb & 3;
    int tid = threadIdx.x;
    int w = tid >> 5, lane = tid & 31;
    int lh = lane & 3;

    int cnt = g_count[r];
    if (cnt > CAPZ) cnt = CAPZ;
    int q4 = (((cnt + 3) >> 2) + 3) & ~3;  // rows per sub, rounded to multiple of 4
    int begin = sub * q4;
    if (begin > cnt) begin = cnt;
    int end = begin + q4;
    if (end > cnt) end = cnt;
    const int* lst = g_sorted + r * CAPZ;

    float areg[HNUM][4];
#pragma unroll
    for (int h = 0; h < HNUM; h++)
#pragma unroll
        for (int j = 0; j < 4; j++)
            areg[h][j] = g_a[h * DDIM + lane * 4 + j];
    float cper = g_c[lh];

    float acc[4][4];
    float den[4] = {0.f, 0.f, 0.f, 0.f};
#pragma unroll
    for (int k = 0; k < 4; k++)
#pragma unroll
        for (int j = 0; j < 4; j++) acc[k][j] = 0.f;

    // one row's full update; `valid` is warp-uniform (compile-folds on fast path)
    auto dorow = [&](const float4& xv, bool valid) {
        float p0 = areg[0][0] * xv.x;
        p0 = fmaf(areg[0][1], xv.y, p0);
        p0 = fmaf(areg[0][2], xv.z, p0);
        p0 = fmaf(areg[0][3], xv.w, p0);
        float p1 = areg[1][0] * xv.x;
        p1 = fmaf(areg[1][1], xv.y, p1);
        p1 = fmaf(areg[1][2], xv.z, p1);
        p1 = fmaf(areg[1][3], xv.w, p1);
        float p2 = areg[2][0] * xv.x;
        p2 = fmaf(areg[2][1], xv.y, p2);
        p2 = fmaf(areg[2][2], xv.z, p2);
        p2 = fmaf(areg[2][3], xv.w, p2);
        float p3 = areg[3][0] * xv.x;
        p3 = fmaf(areg[3][1], xv.y, p3);
        p3 = fmaf(areg[3][2], xv.z, p3);
        p3 = fmaf(areg[3][3], xv.w, p3);
        bool b0 = lane & 1;
        bool b1 = lane & 2;
        float rA = (b0 ? p1 : p0) + __shfl_xor_sync(F, b0 ? p0 : p1, 1);
        float rB = (b0 ? p3 : p2) + __shfl_xor_sync(F, b0 ? p2 : p3, 1);
        float rr = (b1 ? rB : rA) + __shfl_xor_sync(F, b1 ? rA : rB, 2);
        rr += __shfl_xor_sync(F, rr, 4);
        rr += __shfl_xor_sync(F, rr, 8);
        rr += __shfl_xor_sync(F, rr, 16);
        float e0 = valid ? exp2f(rr + cper) : 0.f;    // coeffs pre-scaled by log2e
        float e1 = __shfl_xor_sync(F, e0, 1);
        float e2 = __shfl_xor_sync(F, e0, 2);
        float e3 = __shfl_xor_sync(F, e0, 3);
        den[0] += e0; den[1] += e1; den[2] += e2; den[3] += e3;
        acc[0][0] = fmaf(e0, xv.x, acc[0][0]);
        acc[0][1] = fmaf(e0, xv.y, acc[0][1]);
        acc[0][2] = fmaf(e0, xv.z, acc[0][2]);
        acc[0][3] = fmaf(e0, xv.w, acc[0][3]);
        acc[1][0] = fmaf(e1, xv.x, acc[1][0]);
        acc[1][1] = fmaf(e1, xv.y, acc[1][1]);
        acc[1][2] = fmaf(e1, xv.z, acc[1][2]);
        acc[1][3] = fmaf(e1, xv.w, acc[1][3]);
        acc[2][0] = fmaf(e2, xv.x, acc[2][0]);
        acc[2][1] = fmaf(e2, xv.y, acc[2][1]);
        acc[2][2] = fmaf(e2, xv.z, acc[2][2]);
        acc[2][3] = fmaf(e2, xv.w, acc[2][3]);
        acc[3][0] = fmaf(e3, xv.x, acc[3][0]);
        acc[3][1] = fmaf(e3, xv.y, acc[3][1]);
        acc[3][2] = fmaf(e3, xv.z, acc[3][2]);
        acc[3][3] = fmaf(e3, xv.w, acc[3][3]);
    };

    auto dogrp = [&](const float4* v, int b) {
        if (b + 4 <= end) {
            dorow(v[0], true);
            dorow(v[1], true);
            dorow(v[2], true);
            dorow(v[3], true);
        } else {
            dorow(v[0], b + 0 < end);
            dorow(v[1], b + 1 < end);
            dorow(v[2], b + 2 < end);
            dorow(v[3], b + 3 < end);
        }
    };

    auto loadgrp = [&](int b, float4* v) {
        if (b + 4 <= end) {
            int4 idx = *(const int4*)(lst + b);  // b is a multiple of 4
            v[0] = __ldcs((const float4*)(x + (size_t)idx.x * DDIM) + lane);
            v[1] = __ldcs((const float4*)(x + (size_t)idx.y * DDIM) + lane);
            v[2] = __ldcs((const float4*)(x + (size_t)idx.z * DDIM) + lane);
            v[3] = __ldcs((const float4*)(x + (size_t)idx.w * DDIM) + lane);
        } else {
            int last = end - 1;
#pragma unroll
            for (int u = 0; u < 4; u++) {
                int i = b + u;
                if (i > last) i = last;
                int n = lst[i];
                v[u] = __ldcs((const float4*)(x + (size_t)n * DDIM) + lane);
            }
        }
    };

    int myb = begin + w * 4;
    if (myb < end) {
        float4 bufA[4], bufB[4];
        loadgrp(myb, bufA);
        int base = myb;
        for (;;) {
            // phase A: bufA current, prefetch into bufB
            int nb = base + 16;
            if (nb < end) {
                loadgrp(nb, bufB);
                dogrp(bufA, base);
                base = nb;
            } else {
                dogrp(bufA, base);
                break;
            }
            // phase B: bufB current, prefetch into bufA
            nb = base + 16;
            if (nb < end) {
                loadgrp(nb, bufA);
                dogrp(bufB, base);
                base = nb;
            } else {
                dogrp(bufB, base);
                break;
            }
        }
    }
    // stage per-warp partials: acc[k] belongs to head lh^k, dims 4*lane..+3
#pragma unroll
    for (int k = 0; k < 4; k++) {
        int h = lh ^ k;
        swacc[w][h][lane * 4 + 0] = acc[k][0];
        swacc[w][h][lane * 4 + 1] = acc[k][1];
        swacc[w][h][lane * 4 + 2] = acc[k][2];
        swacc[w][h][lane * 4 + 3] = acc[k][3];
    }
    if (lane < 4) {
#pragma unroll
        for (int k = 0; k < 4; k++) swden[w][lh ^ k] = den[k];
    }
    __syncthreads();
    // block-reduce across 4 warps and write partials (coalesced)
    for (int p = tid; p < HNUM * DDIM; p += 128) {
        int h = p >> 7, j = p & 127;
        g_pxbar[(size_t)rb * (HNUM * DDIM) + p] =
            swacc[0][h][j] + swacc[1][h][j] + swacc[2][h][j] + swacc[3][h][j];
    }
    if (tid < HNUM)
        g_pden[rb * HNUM + tid] =
            swden[0][tid] + swden[1][tid] + swden[2][tid] + swden[3][tid];

    // ---- last-done sub-block runs finalize for this region ----
    __threadfence();
    __syncthreads();
    if (tid == 0) s_last = (atomicAdd(&g_done[r], 1) == SPLIT - 1);
    __syncthreads();
    if (!s_last) return;
    __threadfence();

    // reduce SPLIT partials (just written -> L2-hot); bypass L1
    for (int p = tid; p < HNUM * DDIM; p += 128) {
        size_t b = (size_t)r * SPLIT * (HNUM * DDIM);
        float s = __ldcg(&g_pxbar[b + p]) + __ldcg(&g_pxbar[b + 512 + p]) +
                  __ldcg(&g_pxbar[b + 1024 + p]) + __ldcg(&g_pxbar[b + 1536 + p]);
        sxbar[p >> 7][p & 127] = s;
    }
    if (tid < HNUM) {
        int b = r * SPLIT * HNUM;
        sden[tid] = __ldcg(&g_pden[b + tid]) + __ldcg(&g_pden[b + 4 + tid]) +
                    __ldcg(&g_pden[b + 8 + tid]) + __ldcg(&g_pden[b + 12 + tid]);
    }
    __syncthreads();

    int rowsel = ((lane >> 4) & 1) | (((lane >> 3) & 1) << 1) | (((lane >> 2) & 1) << 2);
    bool isw = (lane & 3) == 0;
    // ---- stage 1: O = q + (Wv . xbar[head]) / den + bv ; warp w == head w
    {
        float dn = sden[w];
        float inv = (dn > 0.f) ? (1.f / dn) : 0.f;
        float4 xv = ((const float4*)&sxbar[w][0])[lane];
        const float4* Wb = (const float4*)(Wv + (w * 32) * DDIM);
#pragma unroll
        for (int t = 0; t < 4; t++) {
            float s = gemv8_fold(Wb + t * 8 * 32, xv, lane);
            if (isw) {
                int row = w * 32 + t * 8 + rowsel;
                float pooled = (dn > 0.f) ? (s * inv + bv[row]) : 0.f;
                sO[row] = g_q[row] + pooled;
            }
        }
    }
    __syncthreads();
    // ---- stage 2: O2 = O + relu(Wo . O + bo)
    {
        float4 xv = ((const float4*)sO)[lane];
        const float4* Wb = (const float4*)(Wo + (w * 32) * DDIM);
#pragma unroll
        for (int t = 0; t < 4; t++) {
            float s = gemv8_fold(Wb + t * 8 * 32, xv, lane);
            if (isw) {
                int row = w * 32 + t * 8 + rowsel;
                sO2[row] = sO[row] + fmaxf(s + bo[row], 0.f);
            }
        }
    }
    __syncthreads();
    // ---- stage 3: hh = Wg . O2
    {
        float4 xv = ((const float4*)sO2)[lane];
        const float4* Wb = (const float4*)(Wg + (w * 32) * DDIM);
#pragma unroll
        for (int t = 0; t < 4; t++) {
            float s = gemv8_fold(Wb + t * 8 * 32, xv, lane);
            if (isw) {
                int row = w * 32 + t * 8 + rowsel;
                g_hh[r * DDIM + row] = s;
            }
        }
    }
}

// ---- GCN gather (bucketed by dst) + self loop + bias + PReLU ----
__global__ void gather_kernel(const float* __restrict__ bg,
                              const float* __restrict__ prelu_w,
                              float* __restrict__ out) {
    int r = blockIdx.x, i = threadIdx.x;
    int ec = g_ecount[r];
    int ecl = (ec > CAPE) ? CAPE : ec;
    float degr = (float)(ec + 1);
    float disr = rsqrtf(degr);
    float accv = g_hh[r * DDIM + i] / degr;  // self-loop: dis_r^2
    const int* es = g_esrc + r * CAPE;
    for (int k = 0; k < ecl; k++) {
        int src = es[k];
        float nrm = disr * rsqrtf((float)(g_ecount[src] + 1));
        accv = fmaf(nrm, g_hh[src * DDIM + i], accv);
    }
    float v = accv + bg[i];
    out[r * DDIM + i] = (v > 0.f) ? v : prelu_w[i] * v;
}

extern "C" void kernel_launch(void* const* d_in, const int* in_sizes, int n_in,
                              void* d_out, int out_size) {
    const float* x    = (const float*)d_in[0];
    const int*   zone = (const int*)d_in[1];
    const int*   adj  = (const int*)d_in[2];
    const float* S    = (const float*)d_in[3];
    const float* Wq   = (const float*)d_in[4];
    const float* bq   = (const float*)d_in[5];
    const float* Wk   = (const float*)d_in[6];
    const float* bk   = (const float*)d_in[7];
    const float* Wv   = (const float*)d_in[8];
    const float* bv   = (const float*)d_in[9];
    const float* Wo   = (const float*)d_in[10];
    const float* bo   = (const float*)d_in[11];
    const float* Wg   = (const float*)d_in[12];
    const float* bg   = (const float*)d_in[13];
    const float* pw   = (const float*)d_in[14];
    int N = in_sizes[0] / DDIM;
    int E = in_sizes[2] / 2;

    prep_kernel<<<2, 128>>>(S, Wq, bq, Wk, bk);
    int totalT = (N >> 2) + (N & 3) + E;
    scatter_kernel<<<(totalT + 255) / 256, 256>>>(zone, adj, N, E);
    partial_kernel<<<RNUM * SPLIT, 128>>>(x, Wv, bv, Wo, bo, Wg);
    gather_kernel<<<RNUM, DDIM>>>(bg, pw, (float*)d_out);
}